// round 16
// baseline (speedup 1.0000x reference)
#include <cuda_runtime.h>
#include <math.h>

#define BB     8
#define NFULL  8192
#define NPART  2048
#define DLAT   512
#define EPSV   1e-12f

// Single scratch: [pf | fp | pp]
constexpr int PF_OFF = 0;
constexpr int FP_OFF = BB * NFULL;
constexpr int PP_OFF = 2 * BB * NFULL;
constexpr int MIN_TOTAL = 2 * BB * NFULL + BB * NPART;
__device__ float g_min[MIN_TOTAL];

constexpr int RBLKS = 120;
__device__ float g_partial[4 * RBLKS];
__device__ unsigned int g_done;          // zeroed by memset each launch

constexpr int THREADS = 256;              // 8 warps
constexpr int WARPS   = 8;
constexpr int Q       = 8;                // queries per thread (4 packed pairs)
constexpr int QP      = Q / 2;            // 4
constexpr int QPB     = THREADS * Q;      // 2048 queries per task
constexpr int CHUNK   = 256;              // refs per task

typedef unsigned long long u64;

__device__ __forceinline__ u64 pack2(float lo, float hi) {
    u64 r; asm("mov.b64 %0, {%1, %2};" : "=l"(r) : "f"(lo), "f"(hi)); return r;
}
__device__ __forceinline__ void unpack2(u64 v, float& lo, float& hi) {
    asm("mov.b64 {%0, %1}, %2;" : "=f"(lo), "=f"(hi) : "l"(v));
}
__device__ __forceinline__ u64 ffma2(u64 a, u64 b, u64 c) {
    u64 d; asm("fma.rn.f32x2 %0, %1, %2, %3;" : "=l"(d) : "l"(a), "l"(b), "l"(c)); return d;
}
__device__ __forceinline__ u64 fadd2(u64 a, u64 b) {
    u64 d; asm("add.rn.f32x2 %0, %1, %2;" : "=l"(d) : "l"(a), "l"(b)); return d;
}
// Warp-min of a NON-NEGATIVE float via integer redux (bit order == float order).
__device__ __forceinline__ float warp_min_pos(float v) {
    unsigned int r;
    asm("redux.sync.min.u32 %0, %1, 0xffffffff;"
        : "=r"(r) : "r"(__float_as_uint(v)));
    return __uint_as_float(r);
}

// ---------------------------------------------------------------------------
constexpr int RCK       = NFULL / CHUNK;             // 32
constexpr int CHAM_QT   = NFULL / QPB;               // 4
constexpr int SYM_TASKS = CHAM_QT * RCK * BB;        // 1024
constexpr int FID_TASKS = 1 * RCK * BB;              // 256
constexpr int GRID      = SYM_TASKS + FID_TASKS;     // 1280

__global__ __launch_bounds__(THREADS)
void fused_rowmin_kernel(const float* __restrict__ pred,
                         const float* __restrict__ full,
                         const float* __restrict__ partial,
                         float* __restrict__ gmin) {
    __shared__ ulonglong2 tA[CHUNK];            // (pack(x,x), pack(y,y))  4KB
    __shared__ ulonglong2 tB[CHUNK];            // (pack(z,z), pack(w,w))  4KB
    __shared__ float      colmin[WARPS][CHUNK]; // 8KB

    const int tid = threadIdx.x;
    const int wid = tid >> 5;
    const int lid = tid & 31;

    // ---- decode task ----
    const float *q, *r;
    float *rowout;
    bool sym;
    int b, ck, qt, Nq;
    int l = blockIdx.x;
    if (l < SYM_TASKS) {
        sym = true;
        b  = l >> 7;
        int rm = l & 127;
        ck = rm >> 2;
        qt = rm & 3;
        q = pred; r = full; rowout = gmin + PF_OFF; Nq = NFULL;
    } else {
        sym = false;
        l -= SYM_TASKS;
        b  = l >> 5;
        ck = l & 31;
        qt = 0;
        q = partial; r = pred; rowout = gmin + PP_OFF; Nq = NPART;
    }
    const int qbase = qt * QPB;
    const int rbase = ck * CHUNK;

    const float* qb = q + (size_t)b * Nq * 3;
    const float* rb = r + (size_t)b * NFULL * 3;

    // ---- tile load: dup-packed refs ----
    for (int j = tid; j < CHUNK; j += THREADS) {
        int rj = rbase + j;
        float x = rb[rj * 3 + 0];
        float y = rb[rj * 3 + 1];
        float z = rb[rj * 3 + 2];
        float w = 0.5f * (x * x + y * y + z * z);
        ulonglong2 a, bb;
        a.x  = pack2(x, x); a.y  = pack2(y, y);
        bb.x = pack2(z, z); bb.y = pack2(w, w);
        tA[j] = a;
        tB[j] = bb;
    }
    __syncthreads();

    // ---- per-thread queries: 4 packed pairs ----
    u64 nqx[QP], nqy[QP], nqz[QP], up[QP];
    float m0[QP], m1[QP];
    const float* qrow = qb + (size_t)(qbase + tid * Q) * 3;
#pragma unroll
    for (int k = 0; k < QP; k++) {
        float x0 = qrow[6 * k + 0], y0 = qrow[6 * k + 1], z0 = qrow[6 * k + 2];
        float x1 = qrow[6 * k + 3], y1 = qrow[6 * k + 4], z1 = qrow[6 * k + 5];
        nqx[k] = pack2(-x0, -x1);
        nqy[k] = pack2(-y0, -y1);
        nqz[k] = pack2(-z0, -z1);
        up[k]  = pack2(0.5f * (x0 * x0 + y0 * y0 + z0 * z0),
                       0.5f * (x1 * x1 + y1 * y1 + z1 * z1));
        m0[k]  = __int_as_float(0x7f800000);
        m1[k]  = __int_as_float(0x7f800000);
    }

    if (sym) {
        // 4-j groups: front-batched LDS (MLP=8), 4 pipelined reduxes, STS.128
        for (int j4 = 0; j4 < CHUNK; j4 += 4) {
            ulonglong2 A[4], B[4];
#pragma unroll
            for (int jj = 0; jj < 4; jj++) {
                A[jj] = tA[j4 + jj];
                B[jj] = tB[j4 + jj];
            }
            float c[4];
#pragma unroll
            for (int jj = 0; jj < 4; jj++) {
                float cc = __int_as_float(0x7f800000);
#pragma unroll
                for (int k = 0; k < QP; k++) {
                    u64 v = ffma2(nqz[k], B[jj].x, fadd2(B[jj].y, up[k]));
                    v = ffma2(nqy[k], A[jj].y, v);
                    v = ffma2(nqx[k], A[jj].x, v);
                    float s0, s1;
                    unpack2(v, s0, s1);
                    m0[k] = fminf(m0[k], s0);
                    m1[k] = fminf(m1[k], s1);
                    cc = fminf(cc, fminf(s0, s1));
                }
                c[jj] = cc;
            }
            float r0 = warp_min_pos(c[0]);
            float r1 = warp_min_pos(c[1]);
            float r2 = warp_min_pos(c[2]);
            float r3 = warp_min_pos(c[3]);
            if (lid == 0)
                *reinterpret_cast<float4*>(&colmin[wid][j4]) =
                    make_float4(r0, r1, r2, r3);
        }
    } else {
#pragma unroll 4
        for (int j = 0; j < CHUNK; j++) {
            ulonglong2 A = tA[j];
            ulonglong2 B = tB[j];
#pragma unroll
            for (int k = 0; k < QP; k++) {
                u64 v = ffma2(nqz[k], B.x, B.y);
                v = ffma2(nqy[k], A.y, v);
                v = ffma2(nqx[k], A.x, v);
                float s0, s1;
                unpack2(v, s0, s1);
                m0[k] = fminf(m0[k], s0);
                m1[k] = fminf(m1[k], s1);
            }
        }
    }

    // ---- row writeback ----
#pragma unroll
    for (int k = 0; k < QP; k++) {
        float u0, u1;
        unpack2(up[k], u0, u1);
        int qi = qbase + tid * Q + 2 * k;
        float a0 = sym ? m0[k] : (u0 + m0[k]);
        float a1 = sym ? m1[k] : (u1 + m1[k]);
        float s0 = fmaxf(a0 + a0, EPSV);
        float s1 = fmaxf(a1 + a1, EPSV);
        atomicMin((unsigned int*)&rowout[(size_t)b * Nq + qi],     __float_as_uint(s0));
        atomicMin((unsigned int*)&rowout[(size_t)b * Nq + qi + 1], __float_as_uint(s1));
    }

    // ---- col writeback (chamfer only): merge 8 warps ----
    if (sym) {
        __syncthreads();
        float* fpout = gmin + FP_OFF;
        for (int j = tid; j < CHUNK; j += THREADS) {
            float v = fminf(
                fminf(fminf(colmin[0][j], colmin[1][j]),
                      fminf(colmin[2][j], colmin[3][j])),
                fminf(fminf(colmin[4][j], colmin[5][j]),
                      fminf(colmin[6][j], colmin[7][j])));
            float sq = fmaxf(v + v, EPSV);
            atomicMin((unsigned int*)&fpout[(size_t)b * NFULL + rbase + j],
                      __float_as_uint(sq));
        }
    }
}

// ---------------------------------------------------------------------------
// Reduce: RBLKS blocks sum partials; last-finishing block folds and emits.
// ---------------------------------------------------------------------------
__global__ __launch_bounds__(256)
void reduce_kernel(const float* __restrict__ gmin,
                   const float* __restrict__ mu,
                   const float* __restrict__ lv,
                   float* __restrict__ partials,
                   unsigned int* __restrict__ done,
                   float* __restrict__ out) {
    const int tid    = threadIdx.x;
    const int stride = gridDim.x * blockDim.x;
    const int g      = blockIdx.x * blockDim.x + tid;

    const float* pf = gmin + PF_OFF;
    const float* fp = gmin + FP_OFF;
    const float* pp = gmin + PP_OFF;

    float s_pf = 0.f, s_fp = 0.f, s_pp = 0.f, s_kl = 0.f;
    for (int i = g; i < BB * NFULL; i += stride) {
        s_pf += sqrtf(pf[i]);
        s_fp += sqrtf(fp[i]);
    }
    for (int i = g; i < BB * NPART; i += stride) s_pp += sqrtf(pp[i]);
    for (int i = g; i < BB * DLAT; i += stride) {
        float m = mu[i], l = lv[i];
        s_kl += 1.0f + l - m * m - expf(l);
    }

    __shared__ float sh[4][8];
#pragma unroll
    for (int off = 16; off > 0; off >>= 1) {
        s_pf += __shfl_down_sync(0xffffffffu, s_pf, off);
        s_fp += __shfl_down_sync(0xffffffffu, s_fp, off);
        s_pp += __shfl_down_sync(0xffffffffu, s_pp, off);
        s_kl += __shfl_down_sync(0xffffffffu, s_kl, off);
    }
    int wid = tid >> 5, lid = tid & 31;
    if (lid == 0) { sh[0][wid] = s_pf; sh[1][wid] = s_fp; sh[2][wid] = s_pp; sh[3][wid] = s_kl; }
    __syncthreads();

    if (tid < 4) {
        float acc = 0.f;
#pragma unroll
        for (int w = 0; w < 8; w++) acc += sh[tid][w];
        partials[tid * RBLKS + blockIdx.x] = acc;
    }

    // last-block folds
    __threadfence();
    __shared__ unsigned int rank;
    if (tid == 0) rank = atomicAdd(done, 1u);
    __syncthreads();
    if (rank == gridDim.x - 1) {
        // 4 warps, one per quantity
        if (tid < 128) {
            int qy = tid >> 5;
            float s = 0.f;
            for (int i = lid; i < RBLKS; i += 32) s += partials[qy * RBLKS + i];
#pragma unroll
            for (int off = 16; off > 0; off >>= 1)
                s += __shfl_down_sync(0xffffffffu, s, off);
            __shared__ float sums[4];
            if (lid == 0) sums[qy] = s;
            __syncthreads();
            if (tid == 0) {
                float inv_nf = 1.0f / (float)(BB * NFULL);
                float cd  = 0.5f * (sums[0] + sums[1]) * inv_nf;
                float fid = sums[2] / (float)(BB * NPART);
                float kl  = -0.5f * sums[3] / (float)BB;
                out[0] = 1.0f * cd + 0.01f * kl + 0.5f * fid;
                out[1] = cd;
                out[2] = kl;
                out[3] = fid;
            }
        }
    }
}

// ---------------------------------------------------------------------------
extern "C" void kernel_launch(void* const* d_in, const int* in_sizes, int n_in,
                              void* d_out, int out_size) {
    const float* pred    = (const float*)d_in[0];
    const float* full    = (const float*)d_in[1];
    const float* partial = (const float*)d_in[2];
    const float* mu      = (const float*)d_in[3];
    const float* logvar  = (const float*)d_in[4];
    float* out = (float*)d_out;

    float *gm, *pt;
    unsigned int* dn;
    cudaGetSymbolAddress((void**)&gm, g_min);
    cudaGetSymbolAddress((void**)&pt, g_partial);
    cudaGetSymbolAddress((void**)&dn, g_done);

    // Init: mins to 0x7f7f7f7f (3.39e38), done counter to 0.
    cudaMemsetAsync(gm, 0x7f, MIN_TOTAL * sizeof(float));
    cudaMemsetAsync(dn, 0, sizeof(unsigned int));

    fused_rowmin_kernel<<<GRID, THREADS>>>(pred, full, partial, gm);

    reduce_kernel<<<RBLKS, 256>>>(gm, mu, logvar, pt, dn, out);
}